// round 1
// baseline (speedup 1.0000x reference)
#include <cuda_runtime.h>

#define N_NODES 100000
#define N_EDGES 1600000
#define D 64

// scratch for support = X @ W   (25.6 MB, __device__ global: allowed)
__device__ float g_support[(size_t)N_NODES * D];

// ---------------------------------------------------------------------------
// Kernel 1: out[n][d] = bias[d]   (float4 vectorized)
// ---------------------------------------------------------------------------
__global__ void init_out_kernel(const float* __restrict__ bias,
                                float* __restrict__ out) {
    int i = blockIdx.x * blockDim.x + threadIdx.x;   // float4 index
    if (i < N_NODES * D / 4) {
        const float4* b4 = (const float4*)bias;      // 16 float4 of bias
        ((float4*)out)[i] = b4[i & 15];
    }
}

// ---------------------------------------------------------------------------
// Kernel 2: g_support = X @ W
// 256 threads/block, 128 rows/block.
// Thread layout: dg = tid&7 (owns cols dg*4..dg*4+3 and 32+dg*4..+3),
//                rq = tid>>3 (owns rows rq*4..rq*4+3 within the block tile).
// W in smem [64][64] row-major: the two float4 loads per k are conflict-free
// (8 lanes at 16B stride span all 32 banks). X tile padded to stride 65 so the
// 4 distinct row-broadcast reads per warp hit distinct banks.
// ---------------------------------------------------------------------------
__global__ void __launch_bounds__(256) gemm_kernel(const float* __restrict__ x,
                                                   const float* __restrict__ w) {
    __shared__ float Ws[64 * 64];       // 16 KB
    __shared__ float Xs[128 * 65];      // 33.25 KB (padded)

    const int tid  = threadIdx.x;
    const int base = blockIdx.x * 128;

    // load W (4096 floats = 1024 float4, 4 per thread)
    {
        const float4* w4  = (const float4*)w;
        float4*       Ws4 = (float4*)Ws;
#pragma unroll
        for (int j = 0; j < 4; j++) Ws4[tid + j * 256] = w4[tid + j * 256];
    }
    // load X tile: 128 rows x 16 float4
    for (int j = tid; j < 128 * 16; j += 256) {
        int r  = j >> 4;
        int c4 = j & 15;
        int gr = base + r;
        float4 v = make_float4(0.f, 0.f, 0.f, 0.f);
        if (gr < N_NODES) v = ((const float4*)x)[gr * 16 + c4];
        float* dst = &Xs[r * 65 + c4 * 4];
        dst[0] = v.x; dst[1] = v.y; dst[2] = v.z; dst[3] = v.w;
    }
    __syncthreads();

    const int dg = tid & 7;
    const int rq = tid >> 3;

    float acc[4][8];
#pragma unroll
    for (int i = 0; i < 4; i++)
#pragma unroll
        for (int j = 0; j < 8; j++) acc[i][j] = 0.f;

#pragma unroll 8
    for (int k = 0; k < 64; k++) {
        float4 w0 = *(const float4*)&Ws[k * 64 + dg * 4];
        float4 w1 = *(const float4*)&Ws[k * 64 + 32 + dg * 4];
#pragma unroll
        for (int i = 0; i < 4; i++) {
            float xv = Xs[(rq * 4 + i) * 65 + k];
            acc[i][0] += xv * w0.x;
            acc[i][1] += xv * w0.y;
            acc[i][2] += xv * w0.z;
            acc[i][3] += xv * w0.w;
            acc[i][4] += xv * w1.x;
            acc[i][5] += xv * w1.y;
            acc[i][6] += xv * w1.z;
            acc[i][7] += xv * w1.w;
        }
    }

#pragma unroll
    for (int i = 0; i < 4; i++) {
        int r = base + rq * 4 + i;
        if (r < N_NODES) {
            *(float4*)&g_support[(size_t)r * 64 + dg * 4] =
                make_float4(acc[i][0], acc[i][1], acc[i][2], acc[i][3]);
            *(float4*)&g_support[(size_t)r * 64 + 32 + dg * 4] =
                make_float4(acc[i][4], acc[i][5], acc[i][6], acc[i][7]);
        }
    }
}

// ---------------------------------------------------------------------------
// Kernel 3: edge scatter. 16 threads per edge, each owns a float4 chunk.
// red.global.add.v4.f32: 16 B reduction, no return -> 25.6M LTS ops total.
// support rows are L2-resident (25.6 MB < 126 MB L2).
// ---------------------------------------------------------------------------
__global__ void __launch_bounds__(256) scatter_kernel(const float* __restrict__ adj,
                                                      const int* __restrict__ src,
                                                      const int* __restrict__ dst,
                                                      float* __restrict__ out) {
    unsigned idx = blockIdx.x * 256u + threadIdx.x;
    unsigned e = idx >> 4;
    unsigned c = idx & 15;
    if (e < N_EDGES) {
        int   s = src[e];
        int   d = dst[e];
        float a = adj[e];
        float4 v = ((const float4*)(g_support + (size_t)s * 64))[c];
        float* op = out + (size_t)d * 64 + c * 4;
        asm volatile("red.global.add.v4.f32 [%0], {%1, %2, %3, %4};"
                     :: "l"(op), "f"(v.x * a), "f"(v.y * a),
                        "f"(v.z * a), "f"(v.w * a)
                     : "memory");
    }
}

// ---------------------------------------------------------------------------
extern "C" void kernel_launch(void* const* d_in, const int* in_sizes, int n_in,
                              void* d_out, int out_size) {
    const float* x    = (const float*)d_in[0];   // [N_NODES, 64]
    const float* w    = (const float*)d_in[1];   // [64, 64]
    const float* bias = (const float*)d_in[2];   // [64]
    const float* adj  = (const float*)d_in[3];   // [N_EDGES]
    const int*   src  = (const int*)d_in[4];     // [N_EDGES]
    const int*   dst  = (const int*)d_in[5];     // [N_EDGES]
    float*       out  = (float*)d_out;           // [N_NODES, 64]

    (void)in_sizes; (void)n_in; (void)out_size;

    // 1) out = bias (broadcast)
    {
        int total4 = N_NODES * D / 4;
        init_out_kernel<<<(total4 + 255) / 256, 256>>>(bias, out);
    }
    // 2) g_support = X @ W
    {
        int blocks = (N_NODES + 127) / 128;   // 782
        gemm_kernel<<<blocks, 256>>>(x, w);
    }
    // 3) out[dst] += adj * support[src]
    {
        long long total = (long long)N_EDGES * 16;
        int blocks = (int)((total + 255) / 256);  // 100000
        scatter_kernel<<<blocks, 256>>>(adj, src, dst, out);
    }
}

// round 2
// speedup vs baseline: 1.1164x; 1.1164x over previous
#include <cuda_runtime.h>

#define N_NODES 100000
#define N_EDGES 1600000
#define D 64
#define SCAN_BLK 1024
#define NB ((N_NODES + SCAN_BLK - 1) / SCAN_BLK)   // 98

// ---------------------------------------------------------------------------
// device scratch (static globals: allowed; no runtime allocation)
// ---------------------------------------------------------------------------
__device__ float g_support[(size_t)N_NODES * D];   // X @ W      (25.6 MB)
__device__ int   g_counts[N_NODES];                // degree histogram
__device__ int   g_offs[N_NODES + 1];              // CSR row offsets
__device__ int   g_cur[N_NODES];                   // fill cursors
__device__ int   g_bsums[NB];                      // per-block scan sums
__device__ int   g_bscan[NB];                      // scanned block sums
__device__ int2  g_csr[N_EDGES];                   // (src, bitcast(adj)) by dst

// ---------------------------------------------------------------------------
// GEMM: g_support = X @ W   (unchanged from round 1)
// ---------------------------------------------------------------------------
__global__ void __launch_bounds__(256) gemm_kernel(const float* __restrict__ x,
                                                   const float* __restrict__ w) {
    __shared__ float Ws[64 * 64];
    __shared__ float Xs[128 * 65];

    const int tid  = threadIdx.x;
    const int base = blockIdx.x * 128;

    {
        const float4* w4  = (const float4*)w;
        float4*       Ws4 = (float4*)Ws;
#pragma unroll
        for (int j = 0; j < 4; j++) Ws4[tid + j * 256] = w4[tid + j * 256];
    }
    for (int j = tid; j < 128 * 16; j += 256) {
        int r  = j >> 4;
        int c4 = j & 15;
        int gr = base + r;
        float4 v = make_float4(0.f, 0.f, 0.f, 0.f);
        if (gr < N_NODES) v = ((const float4*)x)[gr * 16 + c4];
        float* dst = &Xs[r * 65 + c4 * 4];
        dst[0] = v.x; dst[1] = v.y; dst[2] = v.z; dst[3] = v.w;
    }
    __syncthreads();

    const int dg = tid & 7;
    const int rq = tid >> 3;

    float acc[4][8];
#pragma unroll
    for (int i = 0; i < 4; i++)
#pragma unroll
        for (int j = 0; j < 8; j++) acc[i][j] = 0.f;

#pragma unroll 8
    for (int k = 0; k < 64; k++) {
        float4 w0 = *(const float4*)&Ws[k * 64 + dg * 4];
        float4 w1 = *(const float4*)&Ws[k * 64 + 32 + dg * 4];
#pragma unroll
        for (int i = 0; i < 4; i++) {
            float xv = Xs[(rq * 4 + i) * 65 + k];
            acc[i][0] += xv * w0.x;  acc[i][1] += xv * w0.y;
            acc[i][2] += xv * w0.z;  acc[i][3] += xv * w0.w;
            acc[i][4] += xv * w1.x;  acc[i][5] += xv * w1.y;
            acc[i][6] += xv * w1.z;  acc[i][7] += xv * w1.w;
        }
    }

#pragma unroll
    for (int i = 0; i < 4; i++) {
        int r = base + rq * 4 + i;
        if (r < N_NODES) {
            *(float4*)&g_support[(size_t)r * 64 + dg * 4] =
                make_float4(acc[i][0], acc[i][1], acc[i][2], acc[i][3]);
            *(float4*)&g_support[(size_t)r * 64 + 32 + dg * 4] =
                make_float4(acc[i][4], acc[i][5], acc[i][6], acc[i][7]);
        }
    }
}

// ---------------------------------------------------------------------------
// CSR build
// ---------------------------------------------------------------------------
__global__ void zero_counts_kernel() {
    int i = blockIdx.x * 256 + threadIdx.x;
    if (i < N_NODES) g_counts[i] = 0;
}

__global__ void hist_kernel(const int* __restrict__ dst) {
    int e = blockIdx.x * 256 + threadIdx.x;
    if (e < N_EDGES) atomicAdd(&g_counts[dst[e]], 1);
}

// per-block exclusive scan of g_counts -> g_offs (local), block total -> g_bsums
__global__ void __launch_bounds__(SCAN_BLK) scan_block_kernel() {
    __shared__ int warp_sums[32];
    int i    = blockIdx.x * SCAN_BLK + threadIdx.x;
    int lane = threadIdx.x & 31;
    int wid  = threadIdx.x >> 5;
    int v = (i < N_NODES) ? g_counts[i] : 0;

    int s = v;
#pragma unroll
    for (int d = 1; d < 32; d <<= 1) {
        int t = __shfl_up_sync(0xffffffffu, s, d);
        if (lane >= d) s += t;
    }
    if (lane == 31) warp_sums[wid] = s;
    __syncthreads();
    if (wid == 0) {
        int ws = warp_sums[lane];
        int ss = ws;
#pragma unroll
        for (int d = 1; d < 32; d <<= 1) {
            int t = __shfl_up_sync(0xffffffffu, ss, d);
            if (lane >= d) ss += t;
        }
        warp_sums[lane] = ss - ws;                 // exclusive warp offsets
        if (lane == 31) g_bsums[blockIdx.x] = ss;  // block total
    }
    __syncthreads();
    if (i < N_NODES) g_offs[i] = (s - v) + warp_sums[wid];
}

// exclusive scan of the NB block sums (NB = 98 <= 128)
__global__ void scan_bsums_kernel() {
    __shared__ int ws[4];
    int lane = threadIdx.x & 31;
    int wid  = threadIdx.x >> 5;
    int i = threadIdx.x;
    int v = (i < NB) ? g_bsums[i] : 0;
    int s = v;
#pragma unroll
    for (int d = 1; d < 32; d <<= 1) {
        int t = __shfl_up_sync(0xffffffffu, s, d);
        if (lane >= d) s += t;
    }
    if (lane == 31) ws[wid] = s;
    __syncthreads();
    if (threadIdx.x == 0) {
        int a = 0;
#pragma unroll
        for (int w = 0; w < 4; w++) { int t = ws[w]; ws[w] = a; a += t; }
    }
    __syncthreads();
    if (i < NB) g_bscan[i] = (s - v) + ws[wid];
}

__global__ void add_offsets_kernel() {
    int i = blockIdx.x * 256 + threadIdx.x;
    if (i < N_NODES) {
        int o = g_offs[i] + g_bscan[i >> 10];
        g_offs[i] = o;
        g_cur[i]  = o;
    }
    if (i == 0) g_offs[N_NODES] = N_EDGES;
}

__global__ void fill_kernel(const int* __restrict__ src,
                            const int* __restrict__ dst,
                            const float* __restrict__ adj) {
    int e = blockIdx.x * 256 + threadIdx.x;
    if (e < N_EDGES) {
        int p = atomicAdd(&g_cur[dst[e]], 1);
        g_csr[p] = make_int2(src[e], __float_as_int(adj[e]));
    }
}

// ---------------------------------------------------------------------------
// Gather: one 16-lane half-warp per dst node; lane l owns float4 chunk l.
// Writes out = bias + sum directly (no atomics, no init pass).
// ---------------------------------------------------------------------------
__global__ void __launch_bounds__(256) gather_kernel(const float* __restrict__ bias,
                                                     float* __restrict__ out) {
    int tid  = blockIdx.x * 256 + threadIdx.x;
    int node = tid >> 4;         // 100000 * 16 threads exactly
    int l    = tid & 15;

    int start = g_offs[node];
    int deg   = g_offs[node + 1] - start;
    // warp-uniform bound (max of the two half-warps) so shfl masks stay legal
    int degmax = max(deg, __shfl_xor_sync(0xffffffffu, deg, 16));

    float4 acc = make_float4(0.f, 0.f, 0.f, 0.f);

    for (int c = 0; c < degmax; c += 16) {
        int2 ev = make_int2(0, 0);                 // s=0, v=0.0f default
        if (c + l < deg) ev = g_csr[start + c + l];
        int lim = min(16, degmax - c);             // warp-uniform
        for (int i = 0; i < lim; i++) {
            int   s = __shfl_sync(0xffffffffu, ev.x, i, 16);
            float v = __int_as_float(__shfl_sync(0xffffffffu, ev.y, i, 16));
            float4 sv = *(const float4*)&g_support[s * 64 + l * 4];
            acc.x += v * sv.x;
            acc.y += v * sv.y;
            acc.z += v * sv.z;
            acc.w += v * sv.w;
        }
    }

    float4 b = ((const float4*)bias)[l];
    acc.x += b.x; acc.y += b.y; acc.z += b.z; acc.w += b.w;
    ((float4*)out)[node * 16 + l] = acc;
}

// ---------------------------------------------------------------------------
extern "C" void kernel_launch(void* const* d_in, const int* in_sizes, int n_in,
                              void* d_out, int out_size) {
    const float* x    = (const float*)d_in[0];   // [N_NODES, 64]
    const float* w    = (const float*)d_in[1];   // [64, 64]
    const float* bias = (const float*)d_in[2];   // [64]
    const float* adj  = (const float*)d_in[3];   // [N_EDGES]
    const int*   src  = (const int*)d_in[4];     // [N_EDGES]
    const int*   dst  = (const int*)d_in[5];     // [N_EDGES]
    float*       out  = (float*)d_out;           // [N_NODES, 64]

    (void)in_sizes; (void)n_in; (void)out_size;

    const int nblk = (N_NODES + 255) / 256;      // 391
    const int eblk = (N_EDGES + 255) / 256;      // 6250

    gemm_kernel<<<(N_NODES + 127) / 128, 256>>>(x, w);

    zero_counts_kernel<<<nblk, 256>>>();
    hist_kernel<<<eblk, 256>>>(dst);
    scan_block_kernel<<<NB, SCAN_BLK>>>();
    scan_bsums_kernel<<<1, 128>>>();
    add_offsets_kernel<<<nblk, 256>>>();
    fill_kernel<<<eblk, 256>>>(src, dst, adj);

    gather_kernel<<<(N_NODES * 16) / 256, 256>>>(bias, out);
}

// round 3
// speedup vs baseline: 1.2596x; 1.1283x over previous
#include <cuda_runtime.h>
#include <cuda_fp16.h>

#define N_NODES 100000
#define N_EDGES 1600000
#define D 64
#define SCAN_BLK 1024
#define NB ((N_NODES + SCAN_BLK - 1) / SCAN_BLK)   // 98

// ---------------------------------------------------------------------------
// device scratch
// ---------------------------------------------------------------------------
__device__ __align__(16) __half2 g_supp_h[(size_t)N_NODES * 32];  // X@W in fp16 (12.8 MB)
__device__ int   g_counts[N_NODES];
__device__ int   g_offs[N_NODES + 1];
__device__ int   g_cur[N_NODES];
__device__ int   g_bsums[NB];
__device__ int2  g_csr[N_EDGES];                   // (src, bitcast(adj)) grouped by dst

union U8 { uint2 u; __half2 h[2]; };

// ---------------------------------------------------------------------------
// GEMM: g_supp_h = fp16(X @ W).  Also zeroes g_counts (free rider).
// ---------------------------------------------------------------------------
__global__ void __launch_bounds__(256) gemm_kernel(const float* __restrict__ x,
                                                   const float* __restrict__ w) {
    __shared__ float Ws[64 * 64];
    __shared__ float Xs[128 * 65];

    const int tid  = threadIdx.x;
    const int base = blockIdx.x * 128;

    // zero the histogram counters (grid covers 782*256 = 200192 > N_NODES)
    {
        int zi = blockIdx.x * 256 + tid;
        if (zi < N_NODES) g_counts[zi] = 0;
    }

    {
        const float4* w4  = (const float4*)w;
        float4*       Ws4 = (float4*)Ws;
#pragma unroll
        for (int j = 0; j < 4; j++) Ws4[tid + j * 256] = w4[tid + j * 256];
    }
    for (int j = tid; j < 128 * 16; j += 256) {
        int r  = j >> 4;
        int c4 = j & 15;
        int gr = base + r;
        float4 v = make_float4(0.f, 0.f, 0.f, 0.f);
        if (gr < N_NODES) v = ((const float4*)x)[gr * 16 + c4];
        float* dst = &Xs[r * 65 + c4 * 4];
        dst[0] = v.x; dst[1] = v.y; dst[2] = v.z; dst[3] = v.w;
    }
    __syncthreads();

    const int dg = tid & 7;
    const int rq = tid >> 3;

    float acc[4][8];
#pragma unroll
    for (int i = 0; i < 4; i++)
#pragma unroll
        for (int j = 0; j < 8; j++) acc[i][j] = 0.f;

#pragma unroll 8
    for (int k = 0; k < 64; k++) {
        float4 w0 = *(const float4*)&Ws[k * 64 + dg * 4];
        float4 w1 = *(const float4*)&Ws[k * 64 + 32 + dg * 4];
#pragma unroll
        for (int i = 0; i < 4; i++) {
            float xv = Xs[(rq * 4 + i) * 65 + k];
            acc[i][0] += xv * w0.x;  acc[i][1] += xv * w0.y;
            acc[i][2] += xv * w0.z;  acc[i][3] += xv * w0.w;
            acc[i][4] += xv * w1.x;  acc[i][5] += xv * w1.y;
            acc[i][6] += xv * w1.z;  acc[i][7] += xv * w1.w;
        }
    }

#pragma unroll
    for (int i = 0; i < 4; i++) {
        int r = base + rq * 4 + i;
        if (r < N_NODES) {
            U8 a, b;
            a.h[0] = __floats2half2_rn(acc[i][0], acc[i][1]);
            a.h[1] = __floats2half2_rn(acc[i][2], acc[i][3]);
            b.h[0] = __floats2half2_rn(acc[i][4], acc[i][5]);
            b.h[1] = __floats2half2_rn(acc[i][6], acc[i][7]);
            *(uint2*)&g_supp_h[(size_t)r * 32 + dg * 2]      = a.u;  // cols dg*4..+3
            *(uint2*)&g_supp_h[(size_t)r * 32 + 16 + dg * 2] = b.u;  // cols 32+dg*4..+3
        }
    }
}

// ---------------------------------------------------------------------------
// CSR build
// ---------------------------------------------------------------------------
__global__ void hist_kernel(const int* __restrict__ dst) {
    int e = blockIdx.x * 256 + threadIdx.x;
    if (e < N_EDGES) atomicAdd(&g_counts[dst[e]], 1);
}

__global__ void __launch_bounds__(SCAN_BLK) scan_block_kernel() {
    __shared__ int warp_sums[32];
    int i    = blockIdx.x * SCAN_BLK + threadIdx.x;
    int lane = threadIdx.x & 31;
    int wid  = threadIdx.x >> 5;
    int v = (i < N_NODES) ? g_counts[i] : 0;

    int s = v;
#pragma unroll
    for (int d = 1; d < 32; d <<= 1) {
        int t = __shfl_up_sync(0xffffffffu, s, d);
        if (lane >= d) s += t;
    }
    if (lane == 31) warp_sums[wid] = s;
    __syncthreads();
    if (wid == 0) {
        int ws = warp_sums[lane];
        int ss = ws;
#pragma unroll
        for (int d = 1; d < 32; d <<= 1) {
            int t = __shfl_up_sync(0xffffffffu, ss, d);
            if (lane >= d) ss += t;
        }
        warp_sums[lane] = ss - ws;
        if (lane == 31) g_bsums[blockIdx.x] = ss;
    }
    __syncthreads();
    if (i < N_NODES) g_offs[i] = (s - v) + warp_sums[wid];
}

// scans the 98 block sums locally, then adds to offsets; writes cursors
__global__ void __launch_bounds__(256) add_offsets_kernel() {
    __shared__ int sb[128];
    __shared__ int wsum[4];
    int t    = threadIdx.x;
    int lane = t & 31;
    int wid  = t >> 5;

    int v = 0, s = 0;
    if (t < 128) {
        v = (t < NB) ? g_bsums[t] : 0;
        s = v;
#pragma unroll
        for (int d = 1; d < 32; d <<= 1) {
            int tt = __shfl_up_sync(0xffffffffu, s, d);
            if (lane >= d) s += tt;
        }
        if (lane == 31) wsum[wid] = s;
    }
    __syncthreads();
    if (t == 0) {
        int a = 0;
#pragma unroll
        for (int w2 = 0; w2 < 4; w2++) { int tmp = wsum[w2]; wsum[w2] = a; a += tmp; }
    }
    __syncthreads();
    if (t < 128) sb[t] = (s - v) + wsum[wid];
    __syncthreads();

    int i = blockIdx.x * 256 + t;
    if (i < N_NODES) {
        int o = g_offs[i] + sb[i >> 10];
        g_offs[i] = o;
        g_cur[i]  = o;
    }
    if (i == 0) g_offs[N_NODES] = N_EDGES;
}

__global__ void fill_kernel(const int* __restrict__ src,
                            const int* __restrict__ dst,
                            const float* __restrict__ adj) {
    int e = blockIdx.x * 256 + threadIdx.x;
    if (e < N_EDGES) {
        int p = atomicAdd(&g_cur[dst[e]], 1);
        g_csr[p] = make_int2(src[e], __float_as_int(adj[e]));
    }
}

// ---------------------------------------------------------------------------
// Gather: 8 lanes per dst node; lane l owns output cols l*8..l*8+7.
// Edge records broadcast-loaded by all 8 lanes (no shuffles); support row is
// exactly one 128B L2 line per edge. Writes out = bias + sum directly.
// ---------------------------------------------------------------------------
__global__ void __launch_bounds__(256) gather_kernel(const float* __restrict__ bias,
                                                     float* __restrict__ out) {
    int tid  = blockIdx.x * 256 + threadIdx.x;
    int node = tid >> 3;          // grid is exact: 100000*8/256 = 3125 blocks
    int l    = tid & 7;

    int e0 = g_offs[node];
    int e1 = g_offs[node + 1];

    float2 a0 = make_float2(0.f, 0.f), a1 = a0, a2 = a0, a3 = a0;

    for (int e = e0; e < e1; e++) {
        int2  ev = __ldg(&g_csr[e]);               // broadcast across 8 lanes
        float v  = __int_as_float(ev.y);
        union { uint4 u; __half2 h[4]; } r;
        r.u = *(const uint4*)(g_supp_h + ((size_t)ev.x << 5) + (l << 2));
        float2 f0 = __half22float2(r.h[0]);
        float2 f1 = __half22float2(r.h[1]);
        float2 f2 = __half22float2(r.h[2]);
        float2 f3 = __half22float2(r.h[3]);
        a0.x += v * f0.x;  a0.y += v * f0.y;
        a1.x += v * f1.x;  a1.y += v * f1.y;
        a2.x += v * f2.x;  a2.y += v * f2.y;
        a3.x += v * f3.x;  a3.y += v * f3.y;
    }

    float4 b0 = ((const float4*)bias)[l * 2];
    float4 b1 = ((const float4*)bias)[l * 2 + 1];
    float* op = out + (size_t)node * 64 + l * 8;
    *(float4*)op       = make_float4(a0.x + b0.x, a0.y + b0.y, a1.x + b0.z, a1.y + b0.w);
    *(float4*)(op + 4) = make_float4(a2.x + b1.x, a2.y + b1.y, a3.x + b1.z, a3.y + b1.w);
}

// ---------------------------------------------------------------------------
extern "C" void kernel_launch(void* const* d_in, const int* in_sizes, int n_in,
                              void* d_out, int out_size) {
    const float* x    = (const float*)d_in[0];
    const float* w    = (const float*)d_in[1];
    const float* bias = (const float*)d_in[2];
    const float* adj  = (const float*)d_in[3];
    const int*   src  = (const int*)d_in[4];
    const int*   dst  = (const int*)d_in[5];
    float*       out  = (float*)d_out;

    (void)in_sizes; (void)n_in; (void)out_size;

    const int nblk = (N_NODES + 255) / 256;      // 391
    const int eblk = (N_EDGES + 255) / 256;      // 6250

    gemm_kernel<<<(N_NODES + 127) / 128, 256>>>(x, w);   // also zeroes counts
    hist_kernel<<<eblk, 256>>>(dst);
    scan_block_kernel<<<NB, SCAN_BLK>>>();
    add_offsets_kernel<<<nblk, 256>>>();                 // includes bsums scan
    fill_kernel<<<eblk, 256>>>(src, dst, adj);
    gather_kernel<<<(N_NODES * 8) / 256, 256>>>(bias, out);
}

// round 4
// speedup vs baseline: 1.3398x; 1.0636x over previous
#include <cuda_runtime.h>
#include <cuda_fp16.h>

#define N_NODES 100000
#define N_EDGES 1600000
#define D 64
#define SCAN_BLK 1024
#define NB ((N_NODES + SCAN_BLK - 1) / SCAN_BLK)   // 98

// ---------------------------------------------------------------------------
// device scratch (all zero-initialized at module load; kernels maintain the
// "zeroed for next launch" invariant themselves -> deterministic every call)
// ---------------------------------------------------------------------------
__device__ __align__(16) __half2 g_supp_h[(size_t)N_NODES * 32];  // X@W fp16 (12.8 MB)
__device__ int                g_counts[N_NODES];     // degree histogram (zeroed by scan)
__device__ int                g_offs[N_NODES + 1];   // CSR offsets
__device__ int                g_cur[N_NODES];        // fill cursors
__device__ unsigned long long g_state[NB];           // lookback (flag<<32 | aggregate), zeroed by fill
__device__ int2               g_csr[N_EDGES];        // (src, bitcast(adj)) grouped by dst

union U8 { uint2 u; __half2 h[2]; };

// ---------------------------------------------------------------------------
// Kernel 1: g_supp_h = fp16(X @ W), with the dst histogram fused in
// (atomic/mem work overlaps the FFMA-bound GEMM).
// ---------------------------------------------------------------------------
__global__ void __launch_bounds__(256) gemm_hist_kernel(const float* __restrict__ x,
                                                        const float* __restrict__ w,
                                                        const int* __restrict__ dst) {
    __shared__ float Ws[64 * 64];
    __shared__ float Xs[128 * 65];

    const int tid  = threadIdx.x;
    const int base = blockIdx.x * 128;

    // fused histogram: grid-stride, coalesced. g_counts zeroed by previous scan.
    {
        int stride = gridDim.x * 256;
        for (int e = blockIdx.x * 256 + tid; e < N_EDGES; e += stride)
            atomicAdd(&g_counts[dst[e]], 1);
    }

    {
        const float4* w4  = (const float4*)w;
        float4*       Ws4 = (float4*)Ws;
#pragma unroll
        for (int j = 0; j < 4; j++) Ws4[tid + j * 256] = w4[tid + j * 256];
    }
    for (int j = tid; j < 128 * 16; j += 256) {
        int r  = j >> 4;
        int c4 = j & 15;
        int gr = base + r;
        float4 v = make_float4(0.f, 0.f, 0.f, 0.f);
        if (gr < N_NODES) v = ((const float4*)x)[gr * 16 + c4];
        float* dp = &Xs[r * 65 + c4 * 4];
        dp[0] = v.x; dp[1] = v.y; dp[2] = v.z; dp[3] = v.w;
    }
    __syncthreads();

    const int dg = tid & 7;
    const int rq = tid >> 3;

    float acc[4][8];
#pragma unroll
    for (int i = 0; i < 4; i++)
#pragma unroll
        for (int j = 0; j < 8; j++) acc[i][j] = 0.f;

#pragma unroll 8
    for (int k = 0; k < 64; k++) {
        float4 w0 = *(const float4*)&Ws[k * 64 + dg * 4];
        float4 w1 = *(const float4*)&Ws[k * 64 + 32 + dg * 4];
#pragma unroll
        for (int i = 0; i < 4; i++) {
            float xv = Xs[(rq * 4 + i) * 65 + k];
            acc[i][0] += xv * w0.x;  acc[i][1] += xv * w0.y;
            acc[i][2] += xv * w0.z;  acc[i][3] += xv * w0.w;
            acc[i][4] += xv * w1.x;  acc[i][5] += xv * w1.y;
            acc[i][6] += xv * w1.z;  acc[i][7] += xv * w1.w;
        }
    }

#pragma unroll
    for (int i = 0; i < 4; i++) {
        int r = base + rq * 4 + i;
        if (r < N_NODES) {
            U8 a, b;
            a.h[0] = __floats2half2_rn(acc[i][0], acc[i][1]);
            a.h[1] = __floats2half2_rn(acc[i][2], acc[i][3]);
            b.h[0] = __floats2half2_rn(acc[i][4], acc[i][5]);
            b.h[1] = __floats2half2_rn(acc[i][6], acc[i][7]);
            *(uint2*)&g_supp_h[(size_t)r * 32 + dg * 2]      = a.u;
            *(uint2*)&g_supp_h[(size_t)r * 32 + 16 + dg * 2] = b.u;
        }
    }
}

// ---------------------------------------------------------------------------
// Kernel 2: single-pass exclusive scan with decoupled lookback.
// Reads g_counts (and re-zeroes it for the next launch's histogram),
// writes g_offs + g_cur. All NB=98 CTAs are co-resident -> no deadlock.
// ---------------------------------------------------------------------------
__global__ void __launch_bounds__(SCAN_BLK) scan_kernel() {
    __shared__ int warp_sums[32];
    __shared__ int s_prefix;

    const int b    = blockIdx.x;
    const int i    = b * SCAN_BLK + threadIdx.x;
    const int lane = threadIdx.x & 31;
    const int wid  = threadIdx.x >> 5;

    int v = 0;
    if (i < N_NODES) { v = g_counts[i]; g_counts[i] = 0; }

    // warp inclusive scan
    int s = v;
#pragma unroll
    for (int d = 1; d < 32; d <<= 1) {
        int t = __shfl_up_sync(0xffffffffu, s, d);
        if (lane >= d) s += t;
    }
    if (lane == 31) warp_sums[wid] = s;
    __syncthreads();

    if (wid == 0) {
        int ws = warp_sums[lane];
        int ss = ws;
#pragma unroll
        for (int d = 1; d < 32; d <<= 1) {
            int t = __shfl_up_sync(0xffffffffu, ss, d);
            if (lane >= d) ss += t;
        }
        warp_sums[lane] = ss - ws;               // exclusive warp offsets
        if (lane == 31) {                        // publish block aggregate
            atomicExch(&g_state[b], (1ULL << 32) | (unsigned)ss);
        }
        // lookback: sum all predecessor aggregates
        int sum = 0;
        for (int p = lane; p < b; p += 32) {
            unsigned long long xv;
            do { xv = atomicAdd(&g_state[p], 0ULL); } while (!(xv >> 32));
            sum += (int)(unsigned)xv;
        }
#pragma unroll
        for (int d = 16; d >= 1; d >>= 1)
            sum += __shfl_xor_sync(0xffffffffu, sum, d);
        if (lane == 0) s_prefix = sum;
    }
    __syncthreads();

    if (i < N_NODES) {
        int o = s_prefix + warp_sums[wid] + (s - v);
        g_offs[i] = o;
        g_cur[i]  = o;
    }
    if (i == 0) g_offs[N_NODES] = N_EDGES;
}

// ---------------------------------------------------------------------------
// Kernel 3: fill CSR; also re-zeroes the lookback state for the next launch.
// ---------------------------------------------------------------------------
__global__ void fill_kernel(const int* __restrict__ src,
                            const int* __restrict__ dst,
                            const float* __restrict__ adj) {
    if (blockIdx.x == 0 && threadIdx.x < NB) g_state[threadIdx.x] = 0ULL;
    int e = blockIdx.x * 256 + threadIdx.x;
    if (e < N_EDGES) {
        int p = atomicAdd(&g_cur[dst[e]], 1);
        g_csr[p] = make_int2(src[e], __float_as_int(adj[e]));
    }
}

// ---------------------------------------------------------------------------
// Kernel 4: gather. 8 lanes per dst node; lane l owns cols l*8..l*8+7.
// Edge loop unrolled x2 for MLP on the L2-latency support loads.
// ---------------------------------------------------------------------------
__global__ void __launch_bounds__(256) gather_kernel(const float* __restrict__ bias,
                                                     float* __restrict__ out) {
    int tid  = blockIdx.x * 256 + threadIdx.x;
    int node = tid >> 3;
    int l    = tid & 7;

    int e0 = g_offs[node];
    int e1 = g_offs[node + 1];

    float2 a0 = make_float2(0.f, 0.f), a1 = a0, a2 = a0, a3 = a0;

    int e = e0;
    for (; e + 2 <= e1; e += 2) {
        int2 ev0 = __ldg(&g_csr[e]);
        int2 ev1 = __ldg(&g_csr[e + 1]);
        union { uint4 u; __half2 h[4]; } r0, r1;
        r0.u = *(const uint4*)(g_supp_h + ((size_t)ev0.x << 5) + (l << 2));
        r1.u = *(const uint4*)(g_supp_h + ((size_t)ev1.x << 5) + (l << 2));
        float v0 = __int_as_float(ev0.y);
        float v1 = __int_as_float(ev1.y);
        {
            float2 f0 = __half22float2(r0.h[0]), f1 = __half22float2(r0.h[1]);
            float2 f2 = __half22float2(r0.h[2]), f3 = __half22float2(r0.h[3]);
            a0.x += v0 * f0.x;  a0.y += v0 * f0.y;
            a1.x += v0 * f1.x;  a1.y += v0 * f1.y;
            a2.x += v0 * f2.x;  a2.y += v0 * f2.y;
            a3.x += v0 * f3.x;  a3.y += v0 * f3.y;
        }
        {
            float2 f0 = __half22float2(r1.h[0]), f1 = __half22float2(r1.h[1]);
            float2 f2 = __half22float2(r1.h[2]), f3 = __half22float2(r1.h[3]);
            a0.x += v1 * f0.x;  a0.y += v1 * f0.y;
            a1.x += v1 * f1.x;  a1.y += v1 * f1.y;
            a2.x += v1 * f2.x;  a2.y += v1 * f2.y;
            a3.x += v1 * f3.x;  a3.y += v1 * f3.y;
        }
    }
    if (e < e1) {
        int2 ev = __ldg(&g_csr[e]);
        float v = __int_as_float(ev.y);
        union { uint4 u; __half2 h[4]; } r;
        r.u = *(const uint4*)(g_supp_h + ((size_t)ev.x << 5) + (l << 2));
        float2 f0 = __half22float2(r.h[0]), f1 = __half22float2(r.h[1]);
        float2 f2 = __half22float2(r.h[2]), f3 = __half22float2(r.h[3]);
        a0.x += v * f0.x;  a0.y += v * f0.y;
        a1.x += v * f1.x;  a1.y += v * f1.y;
        a2.x += v * f2.x;  a2.y += v * f2.y;
        a3.x += v * f3.x;  a3.y += v * f3.y;
    }

    float4 b0 = ((const float4*)bias)[l * 2];
    float4 b1 = ((const float4*)bias)[l * 2 + 1];
    float* op = out + (size_t)node * 64 + l * 8;
    *(float4*)op       = make_float4(a0.x + b0.x, a0.y + b0.y, a1.x + b0.z, a1.y + b0.w);
    *(float4*)(op + 4) = make_float4(a2.x + b1.x, a2.y + b1.y, a3.x + b1.z, a3.y + b1.w);
}

// ---------------------------------------------------------------------------
extern "C" void kernel_launch(void* const* d_in, const int* in_sizes, int n_in,
                              void* d_out, int out_size) {
    const float* x    = (const float*)d_in[0];
    const float* w    = (const float*)d_in[1];
    const float* bias = (const float*)d_in[2];
    const float* adj  = (const float*)d_in[3];
    const int*   src  = (const int*)d_in[4];
    const int*   dst  = (const int*)d_in[5];
    float*       out  = (float*)d_out;

    (void)in_sizes; (void)n_in; (void)out_size;

    const int eblk = (N_EDGES + 255) / 256;      // 6250

    gemm_hist_kernel<<<(N_NODES + 127) / 128, 256>>>(x, w, dst);
    scan_kernel<<<NB, SCAN_BLK>>>();
    fill_kernel<<<eblk, 256>>>(src, dst, adj);
    gather_kernel<<<(N_NODES * 8) / 256, 256>>>(bias, out);
}